// round 6
// baseline (speedup 1.0000x reference)
#include <cuda_runtime.h>
#include <math.h>

// BFP quant-dequant: x[8192, 12284] fp32, block=8 along last dim.
// step = 2^(frexp_exp(maxabs) - 7); q = clip(rint(x/step), -128, 127); out = q*step.
// Row = 3071 float4; block of 8 = float4 pair (f, f^1) on adjacent even/odd
// lanes -> shared max via shfl_xor(1). Tail float4 3070 pairs with an inactive
// lane (m=0), matching the reference's zero padding.
// R6 delta: persistent grid-stride (1184 CTAs = 148 SMs x 8), unroll-by-2 so
// 4 independent LDG.128 are in flight per thread, __launch_bounds__ to keep
// regs <= 32 (full occupancy). Streaming hints retained.

#define ROWS 8192
#define F4_PER_ROW 3071          // 12284 / 4
#define TILES_X 6                // 6 * 512 = 3072 float4 slots per row
#define TILES (ROWS * TILES_X)   // 49152
#define NCTA 1184                // 148 SMs * 8 resident CTAs

__device__ __forceinline__ float amax4(const float4& v) {
    return fmaxf(fmaxf(fabsf(v.x), fabsf(v.y)), fmaxf(fabsf(v.z), fabsf(v.w)));
}

__device__ __forceinline__ void qdq4(float4& v, float step, float inv) {
    v.x = fminf(fmaxf(rintf(v.x * inv), -128.0f), 127.0f) * step;
    v.y = fminf(fmaxf(rintf(v.y * inv), -128.0f), 127.0f) * step;
    v.z = fminf(fmaxf(rintf(v.z * inv), -128.0f), 127.0f) * step;
    v.w = fminf(fmaxf(rintf(v.w * inv), -128.0f), 127.0f) * step;
}

__device__ __forceinline__ void make_steps(float m, float& step, float& inv) {
    // m >= 0. For normal m: frexp exponent e = exp_field - 126.
    // step = 2^(e-7) -> field = ef - 6 ; inv = 2^(7-e) -> field = 260 - ef.
    unsigned ef = __float_as_uint(m) >> 23;
    if (ef >= 7u && ef <= 253u) {
        step = __uint_as_float((ef - 6u) << 23);
        inv  = __uint_as_float((260u - ef) << 23);
    } else {
        int e; frexpf(m, &e);          // exact fallback (m==0 or extreme exponent)
        step = ldexpf(1.0f, e - 7);
        inv  = ldexpf(1.0f, 7 - e);
    }
}

// tile t -> (row, bx); slot f0 always valid (<= 2815), f1 valid unless == 3071.
__device__ __forceinline__ void tile_idx(int t, int tid, size_t& i0, size_t& i1, bool& vb) {
    int row = t / TILES_X;
    int bx  = t - row * TILES_X;
    int f0  = bx * 512 + tid;
    int f1  = f0 + 256;
    vb = (f1 < F4_PER_ROW);
    size_t rb = (size_t)row * F4_PER_ROW;
    i0 = rb + f0;
    i1 = rb + f1;
}

__device__ __forceinline__ void qdq_pair(float4& a, float4& b) {
    float ma = amax4(a);
    float mb = amax4(b);
    // Partner half-block lives in the adjacent lane (bit 0 of the f4 index).
    ma = fmaxf(ma, __shfl_xor_sync(0xFFFFFFFFu, ma, 1));
    mb = fmaxf(mb, __shfl_xor_sync(0xFFFFFFFFu, mb, 1));
    float sa, ia, sb, ib;
    make_steps(ma, sa, ia);
    make_steps(mb, sb, ib);
    qdq4(a, sa, ia);
    qdq4(b, sb, ib);
}

__global__ __launch_bounds__(256, 8)
void bfp_kernel(const float4* __restrict__ x, float4* __restrict__ out) {
    const int tid = threadIdx.x;
    int t = blockIdx.x;

    // Unrolled-by-2 grid-stride: 4 independent LDG.128 in flight per thread.
    while (t + NCTA < TILES) {
        size_t i0a, i1a, i0b, i1b;
        bool va, vbb;
        tile_idx(t,        tid, i0a, i1a, va);
        tile_idx(t + NCTA, tid, i0b, i1b, vbb);

        float4 a0 = __ldcs(&x[i0a]);
        float4 b0 = va  ? __ldcs(&x[i1a]) : make_float4(0.f, 0.f, 0.f, 0.f);
        float4 a1 = __ldcs(&x[i0b]);
        float4 b1 = vbb ? __ldcs(&x[i1b]) : make_float4(0.f, 0.f, 0.f, 0.f);

        qdq_pair(a0, b0);
        qdq_pair(a1, b1);

        __stcs(&out[i0a], a0);
        if (va)  __stcs(&out[i1a], b0);
        __stcs(&out[i0b], a1);
        if (vbb) __stcs(&out[i1b], b1);

        t += 2 * NCTA;
    }
    if (t < TILES) {
        size_t i0, i1;
        bool vb;
        tile_idx(t, tid, i0, i1, vb);
        float4 a = __ldcs(&x[i0]);
        float4 b = vb ? __ldcs(&x[i1]) : make_float4(0.f, 0.f, 0.f, 0.f);
        qdq_pair(a, b);
        __stcs(&out[i0], a);
        if (vb) __stcs(&out[i1], b);
    }
}

extern "C" void kernel_launch(void* const* d_in, const int* in_sizes, int n_in,
                              void* d_out, int out_size) {
    const float4* x = (const float4*)d_in[0];
    float4* out = (float4*)d_out;
    bfp_kernel<<<NCTA, 256>>>(x, out);
}

// round 7
// speedup vs baseline: 1.2390x; 1.2390x over previous
#include <cuda_runtime.h>
#include <math.h>

// BFP quant-dequant: x[8192, 12284] fp32, block=8 along last dim.
// step = 2^(frexp_exp(maxabs) - 7); q = clip(rint(x/step), -128, 127); out = q*step.
// Row = 3071 float4; block of 8 = float4 pair (f, f^1) on adjacent even/odd
// lanes -> shared max via shfl_xor(1). Tail float4 3070 pairs with an inactive
// lane (m=0), matching the reference's zero padding.
// R7 delta vs R5 (best): flat grid, NO loop, each CTA covers 2 adjacent rows
// -> 4 independent batched LDG.128/thread (MLP 4), regs capped at 36 via
// __launch_bounds__(256,7) so occupancy stays ~87%. Streaming hints kept.

#define ROWS 8192
#define F4_PER_ROW 3071          // 12284 / 4
#define CTAS_X 6                 // 6 * 512 = 3072 float4 slots per row
#define GRID_Y (ROWS / 2)        // two rows per CTA

__device__ __forceinline__ float amax4(const float4& v) {
    return fmaxf(fmaxf(fabsf(v.x), fabsf(v.y)), fmaxf(fabsf(v.z), fabsf(v.w)));
}

__device__ __forceinline__ void qdq4(float4& v, float step, float inv) {
    v.x = fminf(fmaxf(rintf(v.x * inv), -128.0f), 127.0f) * step;
    v.y = fminf(fmaxf(rintf(v.y * inv), -128.0f), 127.0f) * step;
    v.z = fminf(fmaxf(rintf(v.z * inv), -128.0f), 127.0f) * step;
    v.w = fminf(fmaxf(rintf(v.w * inv), -128.0f), 127.0f) * step;
}

__device__ __forceinline__ void make_steps(float m, float& step, float& inv) {
    // m >= 0. For normal m: frexp exponent e = exp_field - 126.
    // step = 2^(e-7) -> field = ef - 6 ; inv = 2^(7-e) -> field = 260 - ef.
    unsigned ef = __float_as_uint(m) >> 23;
    if (ef >= 7u && ef <= 253u) {
        step = __uint_as_float((ef - 6u) << 23);
        inv  = __uint_as_float((260u - ef) << 23);
    } else {
        int e; frexpf(m, &e);          // exact fallback (m==0 or extreme exponent)
        step = ldexpf(1.0f, e - 7);
        inv  = ldexpf(1.0f, 7 - e);
    }
}

__device__ __forceinline__ void qdq_pair(float4& a, float4& b) {
    float ma = amax4(a);
    float mb = amax4(b);
    // Partner half-block lives in the adjacent lane (bit 0 of the f4 index).
    ma = fmaxf(ma, __shfl_xor_sync(0xFFFFFFFFu, ma, 1));
    mb = fmaxf(mb, __shfl_xor_sync(0xFFFFFFFFu, mb, 1));
    float sa, ia, sb, ib;
    make_steps(ma, sa, ia);
    make_steps(mb, sb, ib);
    qdq4(a, sa, ia);
    qdq4(b, sb, ib);
}

__global__ __launch_bounds__(256, 7)
void bfp_kernel(const float4* __restrict__ x, float4* __restrict__ out) {
    const int f0 = blockIdx.x * 512 + threadIdx.x;   // <= 2815, always valid
    const int f1 = f0 + 256;                         // invalid only when == 3071
    const bool vb = (f1 < F4_PER_ROW);

    const size_t rb0 = (size_t)(blockIdx.y * 2)     * F4_PER_ROW;
    const size_t rb1 = (size_t)(blockIdx.y * 2 + 1) * F4_PER_ROW;

    // 4 independent coalesced LDG.128 batched up front.
    float4 a0 = __ldcs(&x[rb0 + f0]);
    float4 a1 = __ldcs(&x[rb1 + f0]);
    float4 b0 = vb ? __ldcs(&x[rb0 + f1]) : make_float4(0.f, 0.f, 0.f, 0.f);
    float4 b1 = vb ? __ldcs(&x[rb1 + f1]) : make_float4(0.f, 0.f, 0.f, 0.f);

    qdq_pair(a0, b0);
    qdq_pair(a1, b1);

    __stcs(&out[rb0 + f0], a0);
    if (vb) __stcs(&out[rb0 + f1], b0);
    __stcs(&out[rb1 + f0], a1);
    if (vb) __stcs(&out[rb1 + f1], b1);
}

extern "C" void kernel_launch(void* const* d_in, const int* in_sizes, int n_in,
                              void* d_out, int out_size) {
    const float4* x = (const float4*)d_in[0];
    float4* out = (float4*)d_out;
    dim3 grid(CTAS_X, GRID_Y);
    bfp_kernel<<<grid, 256>>>(x, out);
}

// round 9
// speedup vs baseline: 1.2685x; 1.0238x over previous
#include <cuda_runtime.h>
#include <math.h>

// BFP quant-dequant: x[8192, 12284] fp32, block=8 along last dim.
// step = 2^(frexp_exp(maxabs) - 7); q = clip(rint(x/step), -128, 127); out = q*step.
// 12284 = 3071 float4 per row; block of 8 = float4 pair (f, f^1) held by
// adjacent even/odd lanes -> shared max via shfl_xor(1). Tail float4 3070
// pairs with inactive lane (m=0), matching the reference's zero padding.
// FINAL (== R5, the measured best): flat grid, MLP-2, perfect coalescing,
// evict-first streaming hints, 21 regs / ~80% occupancy. Measured at the
// mixed-R/W HBM ceiling (~6.6 TB/s, 80.8% DRAM active); MLP-4 variants
// (flat, looped, and low-occ) all regressed — see R3/R6/R7 post-mortems.

#define ROWS 8192
#define F4_PER_ROW 3071          // 12284 / 4
#define CTAS_X 6                 // 6 * 512 = 3072 float4 slots per row

__device__ __forceinline__ void qdq4(float4& v, float step, float inv) {
    v.x = fminf(fmaxf(rintf(v.x * inv), -128.0f), 127.0f) * step;
    v.y = fminf(fmaxf(rintf(v.y * inv), -128.0f), 127.0f) * step;
    v.z = fminf(fmaxf(rintf(v.z * inv), -128.0f), 127.0f) * step;
    v.w = fminf(fmaxf(rintf(v.w * inv), -128.0f), 127.0f) * step;
}

__device__ __forceinline__ float amax4(const float4& v) {
    return fmaxf(fmaxf(fabsf(v.x), fabsf(v.y)), fmaxf(fabsf(v.z), fabsf(v.w)));
}

__device__ __forceinline__ void make_steps(float m, float& step, float& inv) {
    // m >= 0. For normal m: frexp exponent e = exp_field - 126.
    // step = 2^(e-7) -> field = ef - 6 ; inv = 2^(7-e) -> field = 260 - ef.
    unsigned ef = __float_as_uint(m) >> 23;
    if (ef >= 7u && ef <= 253u) {
        step = __uint_as_float((ef - 6u) << 23);
        inv  = __uint_as_float((260u - ef) << 23);
    } else {
        int e; frexpf(m, &e);          // exact fallback (m==0 or extreme exponent)
        step = ldexpf(1.0f, e - 7);
        inv  = ldexpf(1.0f, 7 - e);
    }
}

__global__ void bfp_kernel(const float4* __restrict__ x, float4* __restrict__ out) {
    const int row = blockIdx.y;
    const int f0  = blockIdx.x * 512 + threadIdx.x;   // <= 2815, always valid
    const int f1  = f0 + 256;                         // invalid only when == 3071
    const size_t rb = (size_t)row * F4_PER_ROW;

    const bool vb = (f1 < F4_PER_ROW);

    float4 a = __ldcs(&x[rb + f0]);
    float4 b = make_float4(0.f, 0.f, 0.f, 0.f);
    if (vb) b = __ldcs(&x[rb + f1]);

    float ma = amax4(a);
    float mb = amax4(b);

    // Partner half-block lives in adjacent lane (f and f^1 differ in bit 0).
    ma = fmaxf(ma, __shfl_xor_sync(0xFFFFFFFFu, ma, 1));
    mb = fmaxf(mb, __shfl_xor_sync(0xFFFFFFFFu, mb, 1));

    float sa, ia, sb, ib;
    make_steps(ma, sa, ia);
    make_steps(mb, sb, ib);

    qdq4(a, sa, ia);
    qdq4(b, sb, ib);

    __stcs(&out[rb + f0], a);
    if (vb) __stcs(&out[rb + f1], b);
}

extern "C" void kernel_launch(void* const* d_in, const int* in_sizes, int n_in,
                              void* d_out, int out_size) {
    const float4* x = (const float4*)d_in[0];
    float4* out = (float4*)d_out;
    dim3 grid(CTAS_X, ROWS);
    bfp_kernel<<<grid, 256>>>(x, out);
}